// round 2
// baseline (speedup 1.0000x reference)
#include <cuda_runtime.h>

#define C_N 512
#define D_N 256
#define H_N 512
#define M_N 256
#define OH_N 512
#define E_N 261632

// Scratch (no allocations allowed — device globals)
__device__ __align__(16) float g_P[4 * C_N * H_N];    // [t*2+part][c][h], b1 folded into part 0
__device__ __align__(16) float g_agg[C_N * M_N];      // scatter-add target
__device__ __align__(16) float g_h1[C_N * OH_N];
__device__ __align__(16) float g_h2[C_N * OH_N];

// ---------------------------------------------------------------------------
// Generic 64x64-tile fp32 GEMM: C = [relu](A[M,K] @ B[K,N] + bias)
// grid = (N/64, M/64), 256 threads, 4x4 micro-tile per thread, BK=16.
// ---------------------------------------------------------------------------
__global__ __launch_bounds__(256, 4)
void gemm64(const float* __restrict__ A, const float* __restrict__ B,
            const float* __restrict__ bias, float* __restrict__ Cmat,
            int K, int N, int doRelu)
{
    __shared__ __align__(16) float sA[64][20];   // [m][k], pad 20 (16-aligned)
    __shared__ __align__(16) float sB[16][64];   // [k][n]

    int tid = threadIdx.x;
    int tx = tid & 15, ty = tid >> 4;
    int m0 = blockIdx.y * 64, n0 = blockIdx.x * 64;

    float acc[4][4] = {};

    for (int k0 = 0; k0 < K; k0 += 16) {
        // load A tile 64x16 (vectorized)
        {
            int row = tid >> 2, cs = (tid & 3) * 4;
            float4 v = *(const float4*)(A + (m0 + row) * K + k0 + cs);
            *(float4*)&sA[row][cs] = v;
        }
        // load B tile 16x64 (vectorized)
        {
            int kk = tid >> 4, cs = (tid & 15) * 4;
            float4 v = *(const float4*)(B + (k0 + kk) * N + n0 + cs);
            *(float4*)&sB[kk][cs] = v;
        }
        __syncthreads();
        #pragma unroll
        for (int k = 0; k < 16; k++) {
            float a[4];
            #pragma unroll
            for (int i = 0; i < 4; i++) a[i] = sA[ty * 4 + i][k];
            float4 bv = *(const float4*)&sB[k][tx * 4];
            #pragma unroll
            for (int i = 0; i < 4; i++) {
                acc[i][0] = fmaf(a[i], bv.x, acc[i][0]);
                acc[i][1] = fmaf(a[i], bv.y, acc[i][1]);
                acc[i][2] = fmaf(a[i], bv.z, acc[i][2]);
                acc[i][3] = fmaf(a[i], bv.w, acc[i][3]);
            }
        }
        __syncthreads();
    }

    #pragma unroll
    for (int i = 0; i < 4; i++) {
        #pragma unroll
        for (int j = 0; j < 4; j++) {
            int n = n0 + tx * 4 + j;
            float v = acc[i][j] + (bias ? bias[n] : 0.0f);
            if (doRelu) v = fmaxf(v, 0.0f);
            Cmat[(m0 + ty * 4 + i) * N + n] = v;
        }
    }
}

// ---------------------------------------------------------------------------
// Zero the aggregation buffer
// ---------------------------------------------------------------------------
__global__ void zero_agg_kernel()
{
    int i = blockIdx.x * blockDim.x + threadIdx.x;
    if (i < C_N * M_N) g_agg[i] = 0.0f;
}

// ---------------------------------------------------------------------------
// Fused edge kernel:
//   for each edge tile (64 edges) x M tile (128 cols):
//     for t in {0,1}:
//       hidden[e,h] = relu(P_send[t][s_e][h] + P_recv[t][r_e][h])   (b1 folded)
//       msg2 = hidden @ W2[t]  (K = 512)
//       acc += rel[e,t] * relu(msg2 + b2[t])
//     atomicAdd(agg[rec_e], acc)
// 256 threads, 4(edges) x 8(cols) micro-tile per thread, BK = 32.
// ---------------------------------------------------------------------------
__global__ __launch_bounds__(256, 2)
void edge_kernel(const float* __restrict__ W2, const float* __restrict__ b2,
                 const float* __restrict__ rel, const int* __restrict__ send,
                 const int* __restrict__ rec)
{
    __shared__ __align__(16) float sA[64][36];    // hidden tile [e][k], pad 36
    __shared__ __align__(16) float sB[32][128];   // W2 tile [k][n]
    __shared__ int   s_s[64], s_r[64];
    __shared__ float s_rel[64][2];

    int tid = threadIdx.x;
    int tx = tid & 15, ty = tid >> 4;
    int e0 = blockIdx.x * 64;
    int n0 = blockIdx.y * 128;

    if (tid < 64) {
        s_s[tid] = send[e0 + tid];
        s_r[tid] = rec[e0 + tid];
        float2 rr = *(const float2*)(rel + (size_t)(e0 + tid) * 2);
        s_rel[tid][0] = rr.x;
        s_rel[tid][1] = rr.y;
    }
    __syncthreads();

    // A-tile loader assignment: each thread builds 8 hidden values for one edge
    const int la_e = tid >> 2;             // edge 0..63
    const int la_h = (tid & 3) * 8;        // h offset within 32-chunk: 0,8,16,24
    // B-tile loader assignment: each thread loads one 16-wide row segment
    const int lb_k = tid >> 3;             // k 0..31
    const int lb_c = (tid & 7) * 16;       // col 0..112

    const int s_node = s_s[la_e];
    const int r_node = s_r[la_e];

    float acc[4][8] = {};

    #pragma unroll 1
    for (int t = 0; t < 2; t++) {
        const float* PS = g_P + (size_t)(t * 2 + 0) * C_N * H_N + (size_t)s_node * H_N + la_h;
        const float* PR = g_P + (size_t)(t * 2 + 1) * C_N * H_N + (size_t)r_node * H_N + la_h;
        const float* Wt = W2 + (size_t)t * H_N * M_N;

        float acc2[4][8] = {};

        #pragma unroll 1
        for (int k0 = 0; k0 < H_N; k0 += 32) {
            // build hidden tile: relu(PS + PR), 2x float4 per thread
            {
                float4 x0 = *(const float4*)(PS + k0);
                float4 x1 = *(const float4*)(PS + k0 + 4);
                float4 y0 = *(const float4*)(PR + k0);
                float4 y1 = *(const float4*)(PR + k0 + 4);
                float4 h0, h1;
                h0.x = fmaxf(x0.x + y0.x, 0.0f); h0.y = fmaxf(x0.y + y0.y, 0.0f);
                h0.z = fmaxf(x0.z + y0.z, 0.0f); h0.w = fmaxf(x0.w + y0.w, 0.0f);
                h1.x = fmaxf(x1.x + y1.x, 0.0f); h1.y = fmaxf(x1.y + y1.y, 0.0f);
                h1.z = fmaxf(x1.z + y1.z, 0.0f); h1.w = fmaxf(x1.w + y1.w, 0.0f);
                *(float4*)&sA[la_e][la_h]     = h0;
                *(float4*)&sA[la_e][la_h + 4] = h1;
            }
            // load W2 tile 32x128
            {
                const float* src = Wt + (size_t)(k0 + lb_k) * M_N + n0 + lb_c;
                float4 v0 = *(const float4*)(src);
                float4 v1 = *(const float4*)(src + 4);
                float4 v2 = *(const float4*)(src + 8);
                float4 v3 = *(const float4*)(src + 12);
                *(float4*)&sB[lb_k][lb_c]      = v0;
                *(float4*)&sB[lb_k][lb_c + 4]  = v1;
                *(float4*)&sB[lb_k][lb_c + 8]  = v2;
                *(float4*)&sB[lb_k][lb_c + 12] = v3;
            }
            __syncthreads();
            #pragma unroll
            for (int k = 0; k < 32; k++) {
                float a0 = sA[ty * 4 + 0][k];
                float a1 = sA[ty * 4 + 1][k];
                float a2 = sA[ty * 4 + 2][k];
                float a3 = sA[ty * 4 + 3][k];
                float4 b0 = *(const float4*)&sB[k][tx * 8];
                float4 b1v = *(const float4*)&sB[k][tx * 8 + 4];
                acc2[0][0] = fmaf(a0, b0.x, acc2[0][0]); acc2[0][1] = fmaf(a0, b0.y, acc2[0][1]);
                acc2[0][2] = fmaf(a0, b0.z, acc2[0][2]); acc2[0][3] = fmaf(a0, b0.w, acc2[0][3]);
                acc2[0][4] = fmaf(a0, b1v.x, acc2[0][4]); acc2[0][5] = fmaf(a0, b1v.y, acc2[0][5]);
                acc2[0][6] = fmaf(a0, b1v.z, acc2[0][6]); acc2[0][7] = fmaf(a0, b1v.w, acc2[0][7]);
                acc2[1][0] = fmaf(a1, b0.x, acc2[1][0]); acc2[1][1] = fmaf(a1, b0.y, acc2[1][1]);
                acc2[1][2] = fmaf(a1, b0.z, acc2[1][2]); acc2[1][3] = fmaf(a1, b0.w, acc2[1][3]);
                acc2[1][4] = fmaf(a1, b1v.x, acc2[1][4]); acc2[1][5] = fmaf(a1, b1v.y, acc2[1][5]);
                acc2[1][6] = fmaf(a1, b1v.z, acc2[1][6]); acc2[1][7] = fmaf(a1, b1v.w, acc2[1][7]);
                acc2[2][0] = fmaf(a2, b0.x, acc2[2][0]); acc2[2][1] = fmaf(a2, b0.y, acc2[2][1]);
                acc2[2][2] = fmaf(a2, b0.z, acc2[2][2]); acc2[2][3] = fmaf(a2, b0.w, acc2[2][3]);
                acc2[2][4] = fmaf(a2, b1v.x, acc2[2][4]); acc2[2][5] = fmaf(a2, b1v.y, acc2[2][5]);
                acc2[2][6] = fmaf(a2, b1v.z, acc2[2][6]); acc2[2][7] = fmaf(a2, b1v.w, acc2[2][7]);
                acc2[3][0] = fmaf(a3, b0.x, acc2[3][0]); acc2[3][1] = fmaf(a3, b0.y, acc2[3][1]);
                acc2[3][2] = fmaf(a3, b0.z, acc2[3][2]); acc2[3][3] = fmaf(a3, b0.w, acc2[3][3]);
                acc2[3][4] = fmaf(a3, b1v.x, acc2[3][4]); acc2[3][5] = fmaf(a3, b1v.y, acc2[3][5]);
                acc2[3][6] = fmaf(a3, b1v.z, acc2[3][6]); acc2[3][7] = fmaf(a3, b1v.w, acc2[3][7]);
            }
            __syncthreads();
        }

        // per-type epilogue: relu(msg2 + b2) weighted by rel_type
        #pragma unroll
        for (int i = 0; i < 4; i++) {
            float rv = s_rel[ty * 4 + i][t];
            #pragma unroll
            for (int j = 0; j < 8; j++) {
                int n = n0 + tx * 8 + j;
                float v = fmaxf(acc2[i][j] + b2[t * M_N + n], 0.0f);
                acc[i][j] = fmaf(rv, v, acc[i][j]);
            }
        }
    }

    // scatter-add into agg by receiver
    #pragma unroll
    for (int i = 0; i < 4; i++) {
        int rnode = s_r[ty * 4 + i];
        float* dst = g_agg + (size_t)rnode * M_N + n0 + tx * 8;
        #pragma unroll
        for (int j = 0; j < 8; j++)
            atomicAdd(dst + j, acc[i][j]);
    }
}

// ---------------------------------------------------------------------------
// Launch
// ---------------------------------------------------------------------------
extern "C" void kernel_launch(void* const* d_in, const int* in_sizes, int n_in,
                              void* d_out, int out_size)
{
    const float* inputs = (const float*)d_in[0];   // [C, D]
    const float* rel    = (const float*)d_in[1];   // [E, 2]
    const float* W1     = (const float*)d_in[2];   // [T, 2D, H]
    const float* b1     = (const float*)d_in[3];   // [T, H]
    const float* W2     = (const float*)d_in[4];   // [T, H, M]
    const float* b2     = (const float*)d_in[5];   // [T, M]
    const float* Wo1    = (const float*)d_in[6];   // [M, OH]
    const float* bo1    = (const float*)d_in[7];
    const float* Wo2    = (const float*)d_in[8];   // [OH, OH]
    const float* bo2    = (const float*)d_in[9];
    const float* Wo3    = (const float*)d_in[10];  // [OH, D]
    const float* bo3    = (const float*)d_in[11];
    const int* send_idx = (const int*)d_in[12];
    const int* rec_idx  = (const int*)d_in[13];
    float* out = (float*)d_out;

    float *pP, *pAgg, *pH1, *pH2;
    cudaGetSymbolAddress((void**)&pP, g_P);
    cudaGetSymbolAddress((void**)&pAgg, g_agg);
    cudaGetSymbolAddress((void**)&pH1, g_h1);
    cudaGetSymbolAddress((void**)&pH2, g_h2);

    // 1) Per-node layer-1 projections: P[t,part] = inputs @ W1[t][part*D : (part+1)*D]
    //    b1 folded into sender part (part 0).
    for (int t = 0; t < 2; t++) {
        for (int p = 0; p < 2; p++) {
            const float* Bp = W1 + (size_t)(t * 2 + p) * D_N * H_N;
            const float* biasp = (p == 0) ? (b1 + (size_t)t * H_N) : nullptr;
            float* outp = pP + (size_t)(t * 2 + p) * C_N * H_N;
            gemm64<<<dim3(H_N / 64, C_N / 64), 256>>>(inputs, Bp, biasp, outp,
                                                      D_N, H_N, 0);
        }
    }

    // 2) Zero aggregation buffer
    zero_agg_kernel<<<(C_N * M_N + 255) / 256, 256>>>();

    // 3) Fused edge GEMM + weighted relu + scatter-add
    edge_kernel<<<dim3(E_N / 64, M_N / 128), 256>>>(W2, b2, rel, send_idx, rec_idx);

    // 4) Output MLP
    gemm64<<<dim3(OH_N / 64, C_N / 64), 256>>>(pAgg, Wo1, bo1, pH1, M_N, OH_N, 1);
    gemm64<<<dim3(OH_N / 64, C_N / 64), 256>>>(pH1, Wo2, bo2, pH2, OH_N, OH_N, 1);
    gemm64<<<dim3(D_N / 64, C_N / 64), 256>>>(pH2, Wo3, bo3, out, OH_N, D_N, 0);
}

// round 4
// speedup vs baseline: 3.4032x; 3.4032x over previous
#include <cuda_runtime.h>
#include <cstdint>

#define C_N 512
#define D_N 256
#define H_N 512
#define M_N 256
#define OH_N 512
#define E_N 261632

// ---------------------------------------------------------------------------
// Device scratch (no allocations allowed)
// ---------------------------------------------------------------------------
__device__ __align__(16) float g_P[4 * C_N * H_N];     // layer-1 per-node projections
__device__ __align__(16) float g_W2R[2 * H_N * M_N];   // W2 tf32-rounded, native [t][k][n]
__device__ __align__(16) float g_agg[C_N * M_N];       // scatter target
__device__ __align__(16) float g_h1[C_N * OH_N];
__device__ __align__(16) float g_h2[C_N * OH_N];

// ---------------------------------------------------------------------------
// Helpers
// ---------------------------------------------------------------------------
__device__ __forceinline__ uint32_t smem_u32(const void* p) {
    uint32_t a;
    asm("{ .reg .u64 t; cvta.to.shared.u64 t, %1; cvt.u32.u64 %0, t; }" : "=r"(a) : "l"(p));
    return a;
}
__device__ __forceinline__ float f2tf32(float x) {
    uint32_t u; asm("cvt.rna.tf32.f32 %0, %1;" : "=r"(u) : "f"(x));
    return __uint_as_float(u);
}
__device__ __forceinline__ void cp16(uint32_t dst, const void* src) {
    asm volatile("cp.async.cg.shared.global [%0], [%1], 16;" :: "r"(dst), "l"(src));
}
#define CP_COMMIT() asm volatile("cp.async.commit_group;" ::: "memory")
#define CP_WAIT0()  asm volatile("cp.async.wait_group 0;" ::: "memory")

__device__ __forceinline__ void mma_tf32(float* c, const uint32_t* a, const uint32_t* b) {
    asm volatile(
        "mma.sync.aligned.m16n8k8.row.col.f32.tf32.tf32.f32 "
        "{%0,%1,%2,%3}, {%4,%5,%6,%7}, {%8,%9}, {%0,%1,%2,%3};"
        : "+f"(c[0]), "+f"(c[1]), "+f"(c[2]), "+f"(c[3])
        : "r"(a[0]), "r"(a[1]), "r"(a[2]), "r"(a[3]), "r"(b[0]), "r"(b[1]));
}

// ---------------------------------------------------------------------------
// fp32 GEMM body (64x64 tile, 256 thr, 4x4 micro-tile, BK=16) — from R2 (passed)
// ---------------------------------------------------------------------------
__device__ __forceinline__ void gemm64_body(const float* __restrict__ A,
                                            const float* __restrict__ B,
                                            const float* __restrict__ bias,
                                            float* __restrict__ Cmat,
                                            int K, int N, int doRelu, int m0, int n0)
{
    __shared__ __align__(16) float sA[64][20];
    __shared__ __align__(16) float sB[16][64];

    int tid = threadIdx.x;
    int tx = tid & 15, ty = tid >> 4;
    float acc[4][4] = {};

    for (int k0 = 0; k0 < K; k0 += 16) {
        {
            int row = tid >> 2, cs = (tid & 3) * 4;
            float4 v = *(const float4*)(A + (m0 + row) * K + k0 + cs);
            *(float4*)&sA[row][cs] = v;
        }
        {
            int kk = tid >> 4, cs = (tid & 15) * 4;
            float4 v = *(const float4*)(B + (k0 + kk) * N + n0 + cs);
            *(float4*)&sB[kk][cs] = v;
        }
        __syncthreads();
        #pragma unroll
        for (int k = 0; k < 16; k++) {
            float a[4];
            #pragma unroll
            for (int i = 0; i < 4; i++) a[i] = sA[ty * 4 + i][k];
            float4 bv = *(const float4*)&sB[k][tx * 4];
            #pragma unroll
            for (int i = 0; i < 4; i++) {
                acc[i][0] = fmaf(a[i], bv.x, acc[i][0]);
                acc[i][1] = fmaf(a[i], bv.y, acc[i][1]);
                acc[i][2] = fmaf(a[i], bv.z, acc[i][2]);
                acc[i][3] = fmaf(a[i], bv.w, acc[i][3]);
            }
        }
        __syncthreads();
    }

    #pragma unroll
    for (int i = 0; i < 4; i++) {
        #pragma unroll
        for (int j = 0; j < 4; j++) {
            int n = n0 + tx * 4 + j;
            float v = acc[i][j] + (bias ? bias[n] : 0.0f);
            if (doRelu) v = fmaxf(v, 0.0f);
            Cmat[(m0 + ty * 4 + i) * N + n] = v;
        }
    }
}

__global__ __launch_bounds__(256, 4)
void gemm64(const float* __restrict__ A, const float* __restrict__ B,
            const float* __restrict__ bias, float* __restrict__ Cmat,
            int K, int N, int doRelu)
{
    gemm64_body(A, B, bias, Cmat, K, N, doRelu, blockIdx.y * 64, blockIdx.x * 64);
}

__global__ __launch_bounds__(256, 4)
void layer1_gemm(const float* __restrict__ inputs, const float* __restrict__ W1,
                 const float* __restrict__ b1)
{
    int z = blockIdx.z;
    const float* B = W1 + (size_t)z * D_N * H_N;
    const float* bias = ((z & 1) == 0) ? (b1 + (size_t)(z >> 1) * H_N) : nullptr;
    float* outp = g_P + (size_t)z * C_N * H_N;
    gemm64_body(inputs, B, bias, outp, D_N, H_N, 0, blockIdx.y * 64, blockIdx.x * 64);
}

// W2 -> tf32-rounded copy (same layout). 2*512*256/4 elems of float4.
__global__ void round_w2(const float* __restrict__ W2)
{
    int i = blockIdx.x * 256 + threadIdx.x;
    float4 v = ((const float4*)W2)[i];
    v.x = f2tf32(v.x); v.y = f2tf32(v.y);
    v.z = f2tf32(v.z); v.w = f2tf32(v.w);
    ((float4*)g_W2R)[i] = v;
}

__global__ void zero_agg_kernel()
{
    int i = blockIdx.x * blockDim.x + threadIdx.x;
    if (i < C_N * M_N) g_agg[i] = 0.0f;
}

// ---------------------------------------------------------------------------
// Edge kernel: mma.sync tf32. CTA = 128 edges x 128 N cols, K=512, 2 types.
// 8 warps: wm = warp&3 (32-edge strip), wn = warp>>2 (64-col strip).
// Per warp: 2 m16 tiles x 8 n8 tiles. Double-buffered smem, BK=32.
// ---------------------------------------------------------------------------
#define PADA 36                 // floats per A row (stride%32==4 -> conflict-free frags)
#define PADB 136                // floats per B row (stride%32==8 -> conflict-free frags)
#define A_STAGE (128 * PADA)    // 4608 floats
#define B_STAGE (32 * PADB)     // 4352 floats
#define NKC (H_N / 32)          // 16
#define EDGE_SMEM ((2 * A_STAGE + 2 * B_STAGE) * 4)   // 71680 B

__global__ __launch_bounds__(256, 1)
void edge_mma_kernel(const float* __restrict__ b2, const float* __restrict__ rel,
                     const int* __restrict__ send, const int* __restrict__ rec)
{
    extern __shared__ __align__(16) float dsm[];
    float* sAbuf = dsm;                     // 2 stages of [128][PADA]
    float* sBbuf = dsm + 2 * A_STAGE;       // 2 stages of [32][PADB]
    __shared__ float s_rel[128][2];
    __shared__ int   s_r[128];
    __shared__ float s_b2[2][128];

    const int tid  = threadIdx.x;
    const int lane = tid & 31;
    const int warp = tid >> 5;
    const int mb = (warp & 3) * 32;
    const int nb = (warp >> 2) * 64;
    const int e0 = blockIdx.x * 128;
    const int n0 = blockIdx.y * 128;
    const int r4 = lane >> 2, c4 = lane & 3;

    if (tid < 128) {
        s_r[tid] = rec[e0 + tid];
        float2 rr = ((const float2*)rel)[e0 + tid];
        s_rel[tid][0] = rr.x;
        s_rel[tid][1] = rr.y;
        s_b2[0][tid] = b2[n0 + tid];
        s_b2[1][tid] = b2[M_N + n0 + tid];
    }

    // A staging: 2 threads per edge, 16 k-floats each
    const int my_e = tid >> 1;
    const int koff = (tid & 1) * 16;
    const int sn = send[e0 + my_e];
    const int rn = rec[e0 + my_e];

    // B staging: thread -> (row k = tid>>3, 64B chunk at col (tid&7)*16)
    const int brow = tid >> 3;
    const int bcol = (tid & 7) * 16;
    const uint32_t sB_base_u32 = smem_u32(sBbuf);

    float acc[2][8][4];
    float wacc[2][8][4];
    #pragma unroll
    for (int i = 0; i < 2; i++)
        #pragma unroll
        for (int j = 0; j < 8; j++)
            #pragma unroll
            for (int q = 0; q < 4; q++) { acc[i][j][q] = 0.0f; wacc[i][j][q] = 0.0f; }

    float4 pa[4], pb[4];   // A prefetch registers

    #pragma unroll 1
    for (int t = 0; t < 2; t++) {
        const float* PS = g_P + ((size_t)(t * 2 + 0) * C_N + sn) * H_N + koff;
        const float* PR = g_P + ((size_t)(t * 2 + 1) * C_N + rn) * H_N + koff;
        const float* WB = g_W2R + (size_t)t * H_N * M_N + n0 + bcol;

        // ---- prologue: chunk 0 -> buffer 0 ----
        {
            const float* src = WB + (size_t)brow * M_N;
            uint32_t d = sB_base_u32 + (uint32_t)(brow * PADB + bcol) * 4u;
            cp16(d, src); cp16(d + 16, src + 4); cp16(d + 32, src + 8); cp16(d + 48, src + 12);
            CP_COMMIT();
            #pragma unroll
            for (int i = 0; i < 4; i++) {
                pa[i] = ((const float4*)PS)[i];
                pb[i] = ((const float4*)PR)[i];
            }
            float* dst = sAbuf + my_e * PADA + koff;
            #pragma unroll
            for (int i = 0; i < 4; i++) {
                float4 h;
                h.x = f2tf32(fmaxf(pa[i].x + pb[i].x, 0.0f));
                h.y = f2tf32(fmaxf(pa[i].y + pb[i].y, 0.0f));
                h.z = f2tf32(fmaxf(pa[i].z + pb[i].z, 0.0f));
                h.w = f2tf32(fmaxf(pa[i].w + pb[i].w, 0.0f));
                *(float4*)(dst + i * 4) = h;
            }
            CP_WAIT0();
        }
        __syncthreads();

        #pragma unroll 1
        for (int kc = 0; kc < NKC; kc++) {
            const int cur = kc & 1, nxt = cur ^ 1;
            const bool more = (kc + 1 < NKC);
            if (more) {
                // issue next B (cp.async) + next A (ldg into regs)
                const float* src = WB + (size_t)((kc + 1) * 32 + brow) * M_N;
                uint32_t d = sB_base_u32 +
                             (uint32_t)(nxt * B_STAGE + brow * PADB + bcol) * 4u;
                cp16(d, src); cp16(d + 16, src + 4); cp16(d + 32, src + 8); cp16(d + 48, src + 12);
                CP_COMMIT();
                const float* ps = PS + (kc + 1) * 32;
                const float* pr = PR + (kc + 1) * 32;
                #pragma unroll
                for (int i = 0; i < 4; i++) {
                    pa[i] = ((const float4*)ps)[i];
                    pb[i] = ((const float4*)pr)[i];
                }
            }

            // ---- MMA on current buffers ----
            const float* A_s = sAbuf + cur * A_STAGE;
            const float* B_s = sBbuf + cur * B_STAGE;
            #pragma unroll
            for (int ks = 0; ks < 4; ks++) {
                const int k = ks * 8;
                uint32_t af[2][4];
                #pragma unroll
                for (int mt = 0; mt < 2; mt++) {
                    const float* ap = A_s + (mb + mt * 16 + r4) * PADA + k + c4;
                    af[mt][0] = __float_as_uint(ap[0]);
                    af[mt][1] = __float_as_uint(ap[8 * PADA]);
                    af[mt][2] = __float_as_uint(ap[4]);
                    af[mt][3] = __float_as_uint(ap[8 * PADA + 4]);
                }
                #pragma unroll
                for (int nt = 0; nt < 8; nt++) {
                    const float* bp = B_s + (k + c4) * PADB + nb + nt * 8 + r4;
                    uint32_t bf[2];
                    bf[0] = __float_as_uint(bp[0]);
                    bf[1] = __float_as_uint(bp[4 * PADB]);
                    mma_tf32(acc[0][nt], af[0], bf);
                    mma_tf32(acc[1][nt], af[1], bf);
                }
            }

            if (more) {
                // store prefetched A into next buffer
                float* dst = sAbuf + nxt * A_STAGE + my_e * PADA + koff;
                #pragma unroll
                for (int i = 0; i < 4; i++) {
                    float4 h;
                    h.x = f2tf32(fmaxf(pa[i].x + pb[i].x, 0.0f));
                    h.y = f2tf32(fmaxf(pa[i].y + pb[i].y, 0.0f));
                    h.z = f2tf32(fmaxf(pa[i].z + pb[i].z, 0.0f));
                    h.w = f2tf32(fmaxf(pa[i].w + pb[i].w, 0.0f));
                    *(float4*)(dst + i * 4) = h;
                }
                CP_WAIT0();
            }
            __syncthreads();
        }

        // ---- per-type epilogue: relu + bias, weight by rel_type ----
        #pragma unroll
        for (int mt = 0; mt < 2; mt++) {
            const int row0 = mb + mt * 16 + r4;
            const int row1 = row0 + 8;
            const float w0 = s_rel[row0][t];
            const float w1 = s_rel[row1][t];
            #pragma unroll
            for (int nt = 0; nt < 8; nt++) {
                const int col = nb + nt * 8 + 2 * c4;
                const float bb0 = s_b2[t][col];
                const float bb1 = s_b2[t][col + 1];
                wacc[mt][nt][0] += w0 * fmaxf(acc[mt][nt][0] + bb0, 0.0f);
                wacc[mt][nt][1] += w0 * fmaxf(acc[mt][nt][1] + bb1, 0.0f);
                wacc[mt][nt][2] += w1 * fmaxf(acc[mt][nt][2] + bb0, 0.0f);
                wacc[mt][nt][3] += w1 * fmaxf(acc[mt][nt][3] + bb1, 0.0f);
                acc[mt][nt][0] = 0.0f; acc[mt][nt][1] = 0.0f;
                acc[mt][nt][2] = 0.0f; acc[mt][nt][3] = 0.0f;
            }
        }
    }

    // ---- scatter-add by receiver (RED, return unused) ----
    #pragma unroll
    for (int mt = 0; mt < 2; mt++) {
        const int row0 = mb + mt * 16 + r4;
        const int row1 = row0 + 8;
        float* d0 = g_agg + (size_t)s_r[row0] * M_N + n0;
        float* d1 = g_agg + (size_t)s_r[row1] * M_N + n0;
        #pragma unroll
        for (int nt = 0; nt < 8; nt++) {
            const int col = nb + nt * 8 + 2 * c4;
            atomicAdd(d0 + col,     wacc[mt][nt][0]);
            atomicAdd(d0 + col + 1, wacc[mt][nt][1]);
            atomicAdd(d1 + col,     wacc[mt][nt][2]);
            atomicAdd(d1 + col + 1, wacc[mt][nt][3]);
        }
    }
}

// ---------------------------------------------------------------------------
// Launch
// ---------------------------------------------------------------------------
extern "C" void kernel_launch(void* const* d_in, const int* in_sizes, int n_in,
                              void* d_out, int out_size)
{
    const float* inputs = (const float*)d_in[0];
    const float* rel    = (const float*)d_in[1];
    const float* W1     = (const float*)d_in[2];
    const float* b1     = (const float*)d_in[3];
    const float* W2     = (const float*)d_in[4];
    const float* b2     = (const float*)d_in[5];
    const float* Wo1    = (const float*)d_in[6];
    const float* bo1    = (const float*)d_in[7];
    const float* Wo2    = (const float*)d_in[8];
    const float* bo2    = (const float*)d_in[9];
    const float* Wo3    = (const float*)d_in[10];
    const float* bo3    = (const float*)d_in[11];
    const int* send_idx = (const int*)d_in[12];
    const int* rec_idx  = (const int*)d_in[13];
    float* out = (float*)d_out;

    float *pAgg, *pH1, *pH2;
    cudaGetSymbolAddress((void**)&pAgg, g_agg);
    cudaGetSymbolAddress((void**)&pH1, g_h1);
    cudaGetSymbolAddress((void**)&pH2, g_h2);

    cudaFuncSetAttribute(edge_mma_kernel,
                         cudaFuncAttributeMaxDynamicSharedMemorySize, EDGE_SMEM);

    // Prep: round W2 to tf32, layer-1 projections, zero agg
    round_w2<<<(2 * H_N * M_N) / (4 * 256), 256>>>(W2);
    layer1_gemm<<<dim3(H_N / 64, C_N / 64, 4), 256>>>(inputs, W1, b1);
    zero_agg_kernel<<<(C_N * M_N + 255) / 256, 256>>>();

    // Main: tensor-core edge GEMM + fused epilogue + scatter
    edge_mma_kernel<<<dim3(E_N / 128, M_N / 128), 256, EDGE_SMEM>>>(
        b2, rel, send_idx, rec_idx);

    // Output MLP (fp32)
    gemm64<<<dim3(OH_N / 64, C_N / 64), 256>>>(pAgg, Wo1, bo1, pH1, M_N, OH_N, 1);
    gemm64<<<dim3(OH_N / 64, C_N / 64), 256>>>(pH1, Wo2, bo2, pH2, OH_N, OH_N, 1);
    gemm64<<<dim3(D_N / 64, C_N / 64), 256>>>(pH2, Wo3, bo3, out, OH_N, D_N, 0);
}

// round 5
// speedup vs baseline: 6.4570x; 1.8973x over previous
#include <cuda_runtime.h>
#include <cuda_fp16.h>
#include <cstdint>

#define C_N 512
#define D_N 256
#define H_N 512
#define M_N 256
#define OH_N 512
#define E_N 261632

// ---------------------------------------------------------------------------
// Device scratch
// ---------------------------------------------------------------------------
__device__ __align__(16) __half g_Ph[4 * C_N * H_N];    // layer-1 projections, fp16
__device__ __align__(16) __half g_W2TH[2 * M_N * H_N];  // W2 transposed [t][n][k], fp16
__device__ __align__(16) float  g_agg[C_N * M_N];
__device__ __align__(16) float  g_h1[C_N * OH_N];
__device__ __align__(16) float  g_h2[C_N * OH_N];

// ---------------------------------------------------------------------------
// Helpers
// ---------------------------------------------------------------------------
__device__ __forceinline__ uint32_t smem_u32(const void* p) {
    uint32_t a;
    asm("{ .reg .u64 t; cvta.to.shared.u64 t, %1; cvt.u32.u64 %0, t; }" : "=r"(a) : "l"(p));
    return a;
}
__device__ __forceinline__ void cp16(uint32_t dst, const void* src) {
    asm volatile("cp.async.cg.shared.global [%0], [%1], 16;" :: "r"(dst), "l"(src));
}
#define CP_COMMIT() asm volatile("cp.async.commit_group;" ::: "memory")
#define CP_WAIT0()  asm volatile("cp.async.wait_group 0;" ::: "memory")

__device__ __forceinline__ void mma_f16(float* c, const uint32_t* a, const uint32_t* b) {
    asm volatile(
        "mma.sync.aligned.m16n8k16.row.col.f32.f16.f16.f32 "
        "{%0,%1,%2,%3}, {%4,%5,%6,%7}, {%8,%9}, {%0,%1,%2,%3};"
        : "+f"(c[0]), "+f"(c[1]), "+f"(c[2]), "+f"(c[3])
        : "r"(a[0]), "r"(a[1]), "r"(a[2]), "r"(a[3]), "r"(b[0]), "r"(b[1]));
}

// ---------------------------------------------------------------------------
// fp32 GEMM body (64x64 tile, 256 thr) — proven in R2/R4
// ---------------------------------------------------------------------------
__device__ __forceinline__ void gemm64_body(const float* __restrict__ A,
                                            const float* __restrict__ B,
                                            const float* __restrict__ bias,
                                            float* __restrict__ Cf,
                                            __half* __restrict__ Ch,
                                            int K, int N, int doRelu, int m0, int n0)
{
    __shared__ __align__(16) float sA[64][20];
    __shared__ __align__(16) float sB[16][64];

    int tid = threadIdx.x;
    int tx = tid & 15, ty = tid >> 4;
    float acc[4][4] = {};

    for (int k0 = 0; k0 < K; k0 += 16) {
        {
            int row = tid >> 2, cs = (tid & 3) * 4;
            float4 v = *(const float4*)(A + (m0 + row) * K + k0 + cs);
            *(float4*)&sA[row][cs] = v;
        }
        {
            int kk = tid >> 4, cs = (tid & 15) * 4;
            float4 v = *(const float4*)(B + (k0 + kk) * N + n0 + cs);
            *(float4*)&sB[kk][cs] = v;
        }
        __syncthreads();
        #pragma unroll
        for (int k = 0; k < 16; k++) {
            float a[4];
            #pragma unroll
            for (int i = 0; i < 4; i++) a[i] = sA[ty * 4 + i][k];
            float4 bv = *(const float4*)&sB[k][tx * 4];
            #pragma unroll
            for (int i = 0; i < 4; i++) {
                acc[i][0] = fmaf(a[i], bv.x, acc[i][0]);
                acc[i][1] = fmaf(a[i], bv.y, acc[i][1]);
                acc[i][2] = fmaf(a[i], bv.z, acc[i][2]);
                acc[i][3] = fmaf(a[i], bv.w, acc[i][3]);
            }
        }
        __syncthreads();
    }

    #pragma unroll
    for (int i = 0; i < 4; i++) {
        #pragma unroll
        for (int j = 0; j < 4; j++) {
            int n = n0 + tx * 4 + j;
            float v = acc[i][j] + (bias ? bias[n] : 0.0f);
            if (doRelu) v = fmaxf(v, 0.0f);
            if (Cf) Cf[(m0 + ty * 4 + i) * N + n] = v;
            else    Ch[(m0 + ty * 4 + i) * N + n] = __float2half_rn(v);
        }
    }
}

__global__ __launch_bounds__(256, 4)
void gemm64(const float* __restrict__ A, const float* __restrict__ B,
            const float* __restrict__ bias, float* __restrict__ Cmat,
            int K, int N, int doRelu)
{
    gemm64_body(A, B, bias, Cmat, nullptr, K, N, doRelu, blockIdx.y * 64, blockIdx.x * 64);
}

// Layer-1: 4 (type,part) projections -> fp16 P
__global__ __launch_bounds__(256, 4)
void layer1_gemm_h(const float* __restrict__ inputs, const float* __restrict__ W1,
                   const float* __restrict__ b1)
{
    int z = blockIdx.z;
    const float* B = W1 + (size_t)z * D_N * H_N;
    const float* bias = ((z & 1) == 0) ? (b1 + (size_t)(z >> 1) * H_N) : nullptr;
    __half* outp = g_Ph + (size_t)z * C_N * H_N;
    gemm64_body(inputs, B, bias, nullptr, outp, D_N, H_N, 0, blockIdx.y * 64, blockIdx.x * 64);
}

// W2 [t][k][n] -> [t][n][k] fp16
__global__ void transpose_w2_h(const float* __restrict__ W2)
{
    __shared__ float tile[32][33];
    int t = blockIdx.z, k0 = blockIdx.x * 32, n0 = blockIdx.y * 32;
    const float* src = W2 + (size_t)t * H_N * M_N;
    __half* dst = g_W2TH + (size_t)t * M_N * H_N;
    #pragma unroll
    for (int i = 0; i < 4; i++)
        tile[threadIdx.y + i * 8][threadIdx.x] =
            src[(size_t)(k0 + threadIdx.y + i * 8) * M_N + n0 + threadIdx.x];
    __syncthreads();
    #pragma unroll
    for (int i = 0; i < 4; i++)
        dst[(size_t)(n0 + threadIdx.y + i * 8) * H_N + k0 + threadIdx.x] =
            __float2half_rn(tile[threadIdx.x][threadIdx.y + i * 8]);
}

__global__ void zero_agg_kernel()
{
    int i = blockIdx.x * blockDim.x + threadIdx.x;
    if (i < C_N * M_N) g_agg[i] = 0.0f;
}

// ---------------------------------------------------------------------------
// Edge kernel: fp16 mma.sync m16n8k16. CTA = 128 edges x 128 cols, 512 thr.
// 16 warps (4m x 4n), warp tile 32x32 (2 m16 x 4 n8). KC=32, double-buffered.
// Smem row stride 40 halves -> conflict-free frag LDS.
// ---------------------------------------------------------------------------
#define ROWH 40
#define A_STAGE_H (128 * ROWH)   // halves per stage
#define B_STAGE_H (128 * ROWH)
#define NKC (H_N / 32)           // 16
#define EDGE_SMEM ((2 * A_STAGE_H + 2 * B_STAGE_H) * 2)   // 40960 B

__global__ __launch_bounds__(512, 1)
void edge_mma_kernel(const float* __restrict__ b2, const float* __restrict__ rel,
                     const int* __restrict__ send, const int* __restrict__ rec)
{
    extern __shared__ __align__(16) __half dsm[];
    __half* sAbuf = dsm;                       // 2 stages [128][ROWH]
    __half* sBbuf = dsm + 2 * A_STAGE_H;       // 2 stages [128][ROWH]
    __shared__ float s_rel[128][2];
    __shared__ int   s_r[128];
    __shared__ float s_b2[2][128];

    const int tid  = threadIdx.x;
    const int lane = tid & 31;
    const int warp = tid >> 5;
    const int mb = (warp & 3) * 32;
    const int nb = (warp >> 2) * 32;
    const int e0 = blockIdx.x * 128;
    const int n0 = blockIdx.y * 128;
    const int r4 = lane >> 2, c4 = lane & 3;

    if (tid < 128) {
        s_r[tid] = rec[e0 + tid];
        float2 rr = ((const float2*)rel)[e0 + tid];
        s_rel[tid][0] = rr.x;
        s_rel[tid][1] = rr.y;
        s_b2[0][tid] = b2[n0 + tid];
        s_b2[1][tid] = b2[M_N + n0 + tid];
    }

    // A staging: 4 threads per edge, 8 halves (16B) each
    const int le = tid >> 2;         // edge 0..127
    const int lq = tid & 3;          // 16B chunk within 64B k-window
    const int sn = send[e0 + le];
    const int rn = rec[e0 + le];

    // B staging: 1x 16B chunk per thread
    const int brow = tid >> 2;       // W2T row (col of W2) 0..127
    const int bq = tid & 3;
    const uint32_t sB_u32 = smem_u32(sBbuf);

    float acc[2][4][4];
    float wacc[2][4][4];
    #pragma unroll
    for (int i = 0; i < 2; i++)
        #pragma unroll
        for (int j = 0; j < 4; j++)
            #pragma unroll
            for (int q = 0; q < 4; q++) { acc[i][j][q] = 0.0f; wacc[i][j][q] = 0.0f; }

    uint4 pa, pb;
    const __half2 zero2 = __float2half2_rn(0.0f);

    #pragma unroll 1
    for (int t = 0; t < 2; t++) {
        const __half* PS = g_Ph + ((size_t)(t * 2 + 0) * C_N + sn) * H_N + lq * 8;
        const __half* PR = g_Ph + ((size_t)(t * 2 + 1) * C_N + rn) * H_N + lq * 8;
        const __half* WB = g_W2TH + ((size_t)t * M_N + n0 + brow) * H_N + bq * 8;

        // ---- prologue: chunk 0 -> buffer 0 ----
        {
            cp16(sB_u32 + (uint32_t)(brow * ROWH + bq * 8) * 2u, WB);
            CP_COMMIT();
            pa = *(const uint4*)PS;
            pb = *(const uint4*)PR;
            __half2 hh[4];
            const __half2* xa = (const __half2*)&pa;
            const __half2* xb = (const __half2*)&pb;
            #pragma unroll
            for (int i = 0; i < 4; i++)
                hh[i] = __hmax2(__hadd2(xa[i], xb[i]), zero2);
            *(uint4*)(sAbuf + le * ROWH + lq * 8) = *(uint4*)hh;
            CP_WAIT0();
        }
        __syncthreads();

        #pragma unroll 1
        for (int kc = 0; kc < NKC; kc++) {
            const int cur = kc & 1, nxt = cur ^ 1;
            const bool more = (kc + 1 < NKC);
            if (more) {
                cp16(sB_u32 + (uint32_t)(nxt * B_STAGE_H + brow * ROWH + bq * 8) * 2u,
                     WB + (kc + 1) * 32);
                CP_COMMIT();
                pa = *(const uint4*)(PS + (kc + 1) * 32);
                pb = *(const uint4*)(PR + (kc + 1) * 32);
            }

            // ---- MMA on current buffers ----
            const __half* A_s = sAbuf + cur * A_STAGE_H;
            const __half* B_s = sBbuf + cur * B_STAGE_H;
            #pragma unroll
            for (int ks = 0; ks < 2; ks++) {
                uint32_t af[2][4];
                #pragma unroll
                for (int mt = 0; mt < 2; mt++) {
                    const __half* ap = A_s + (mb + mt * 16 + r4) * ROWH + ks * 16 + c4 * 2;
                    af[mt][0] = *(const uint32_t*)(ap);
                    af[mt][1] = *(const uint32_t*)(ap + 8 * ROWH);
                    af[mt][2] = *(const uint32_t*)(ap + 8);
                    af[mt][3] = *(const uint32_t*)(ap + 8 * ROWH + 8);
                }
                #pragma unroll
                for (int nt = 0; nt < 4; nt++) {
                    const __half* bp = B_s + (nb + nt * 8 + r4) * ROWH + ks * 16 + c4 * 2;
                    uint32_t bf[2];
                    bf[0] = *(const uint32_t*)(bp);
                    bf[1] = *(const uint32_t*)(bp + 8);
                    mma_f16(acc[0][nt], af[0], bf);
                    mma_f16(acc[1][nt], af[1], bf);
                }
            }

            if (more) {
                __half2 hh[4];
                const __half2* xa = (const __half2*)&pa;
                const __half2* xb = (const __half2*)&pb;
                #pragma unroll
                for (int i = 0; i < 4; i++)
                    hh[i] = __hmax2(__hadd2(xa[i], xb[i]), zero2);
                *(uint4*)(sAbuf + nxt * A_STAGE_H + le * ROWH + lq * 8) = *(uint4*)hh;
                CP_WAIT0();
            }
            __syncthreads();
        }

        // ---- per-type epilogue: relu + bias, weight by rel_type ----
        #pragma unroll
        for (int mt = 0; mt < 2; mt++) {
            const int row0 = mb + mt * 16 + r4;
            const int row1 = row0 + 8;
            const float w0 = s_rel[row0][t];
            const float w1 = s_rel[row1][t];
            #pragma unroll
            for (int nt = 0; nt < 4; nt++) {
                const int col = nb + nt * 8 + 2 * c4;
                const float bb0 = s_b2[t][col];
                const float bb1 = s_b2[t][col + 1];
                wacc[mt][nt][0] += w0 * fmaxf(acc[mt][nt][0] + bb0, 0.0f);
                wacc[mt][nt][1] += w0 * fmaxf(acc[mt][nt][1] + bb1, 0.0f);
                wacc[mt][nt][2] += w1 * fmaxf(acc[mt][nt][2] + bb0, 0.0f);
                wacc[mt][nt][3] += w1 * fmaxf(acc[mt][nt][3] + bb1, 0.0f);
                acc[mt][nt][0] = 0.0f; acc[mt][nt][1] = 0.0f;
                acc[mt][nt][2] = 0.0f; acc[mt][nt][3] = 0.0f;
            }
        }
    }

    // ---- scatter-add by receiver ----
    #pragma unroll
    for (int mt = 0; mt < 2; mt++) {
        const int row0 = mb + mt * 16 + r4;
        const int row1 = row0 + 8;
        float* d0 = g_agg + (size_t)s_r[row0] * M_N + n0;
        float* d1 = g_agg + (size_t)s_r[row1] * M_N + n0;
        #pragma unroll
        for (int nt = 0; nt < 4; nt++) {
            const int col = nb + nt * 8 + 2 * c4;
            atomicAdd(d0 + col,     wacc[mt][nt][0]);
            atomicAdd(d0 + col + 1, wacc[mt][nt][1]);
            atomicAdd(d1 + col,     wacc[mt][nt][2]);
            atomicAdd(d1 + col + 1, wacc[mt][nt][3]);
        }
    }
}

// ---------------------------------------------------------------------------
// Launch
// ---------------------------------------------------------------------------
extern "C" void kernel_launch(void* const* d_in, const int* in_sizes, int n_in,
                              void* d_out, int out_size)
{
    const float* inputs = (const float*)d_in[0];
    const float* rel    = (const float*)d_in[1];
    const float* W1     = (const float*)d_in[2];
    const float* b1     = (const float*)d_in[3];
    const float* W2     = (const float*)d_in[4];
    const float* b2     = (const float*)d_in[5];
    const float* Wo1    = (const float*)d_in[6];
    const float* bo1    = (const float*)d_in[7];
    const float* Wo2    = (const float*)d_in[8];
    const float* bo2    = (const float*)d_in[9];
    const float* Wo3    = (const float*)d_in[10];
    const float* bo3    = (const float*)d_in[11];
    const int* send_idx = (const int*)d_in[12];
    const int* rec_idx  = (const int*)d_in[13];
    float* out = (float*)d_out;

    float *pAgg, *pH1, *pH2;
    cudaGetSymbolAddress((void**)&pAgg, g_agg);
    cudaGetSymbolAddress((void**)&pH1, g_h1);
    cudaGetSymbolAddress((void**)&pH2, g_h2);

    cudaFuncSetAttribute(edge_mma_kernel,
                         cudaFuncAttributeMaxDynamicSharedMemorySize, EDGE_SMEM);

    // Prep
    transpose_w2_h<<<dim3(H_N / 32, M_N / 32, 2), dim3(32, 8)>>>(W2);
    layer1_gemm_h<<<dim3(H_N / 64, C_N / 64, 4), 256>>>(inputs, W1, b1);
    zero_agg_kernel<<<(C_N * M_N + 255) / 256, 256>>>();

    // Main edge GEMM
    edge_mma_kernel<<<dim3(E_N / 128, M_N / 128), 512, EDGE_SMEM>>>(
        b2, rel, send_idx, rec_idx);

    // Output MLP (fp32)
    gemm64<<<dim3(OH_N / 64, C_N / 64), 256>>>(pAgg, Wo1, bo1, pH1, M_N, OH_N, 1);
    gemm64<<<dim3(OH_N / 64, C_N / 64), 256>>>(pH1, Wo2, bo2, pH2, OH_N, OH_N, 1);
    gemm64<<<dim3(D_N / 64, C_N / 64), 256>>>(pH2, Wo3, bo3, out, OH_N, D_N, 0);
}